// round 8
// baseline (speedup 1.0000x reference)
#include <cuda_runtime.h>
#include <cstdint>

#define CH    128
#define NREL  8
#define MAXN  100000

// Scratch (no cudaMalloc allowed). Total ~58MB static.
__device__ __align__(16) float g_h[(size_t)MAXN * CH];   // 51.2 MB per-relation aggregate
__device__ int   g_cnt[NREL * MAXN];                     // 3.2 MB
__device__ float g_inv[NREL * MAXN];                     // 3.2 MB

// ---------------- per-(relation,dst) edge counts ----------------
__global__ void zero_cnt_kernel(int n) {
    int i = blockIdx.x * blockDim.x + threadIdx.x;
    if (i < n) g_cnt[i] = 0;
}

// edge_index / edge_type are int32 (JAX x64-disabled downgrades int64->int32).
__global__ void count_kernel(const int* __restrict__ ei,
                             const int* __restrict__ et, int E, int N) {
    int e = blockIdx.x * blockDim.x + threadIdx.x;
    if (e >= E) return;
    int dst = ei[E + e];
    int t   = et[e];
    if ((unsigned)dst >= (unsigned)N || (unsigned)t >= NREL) return;  // safety
    atomicAdd(&g_cnt[t * N + dst], 1);
}

__global__ void inv_kernel(int n) {
    int i = blockIdx.x * blockDim.x + threadIdx.x;
    if (i < n) {
        int c = g_cnt[i];
        g_inv[i] = (c > 0) ? 1.0f / (float)c : 0.0f;
    }
}

// ---------------- zero the aggregate buffer ----------------
__global__ void zero_h_kernel(int n4) {
    int i = blockIdx.x * blockDim.x + threadIdx.x;
    if (i < n4) ((float4*)g_h)[i] = make_float4(0.f, 0.f, 0.f, 0.f);
}

// ---------------- per-edge aggregation for relation r ----------------
// One warp per edge; lane l handles floats [4l, 4l+4).
// h[dst] += x[src] * inv_cnt[r,dst]   (mean is linear -> pre-scale per edge)
__global__ void aggregate_kernel(const int* __restrict__ ei,
                                 const int* __restrict__ et,
                                 const float* __restrict__ x,
                                 int r, int E, int N) {
    int w    = (int)((blockIdx.x * (size_t)blockDim.x + threadIdx.x) >> 5);
    int lane = threadIdx.x & 31;
    if (w >= E) return;
    if (et[w] != r) return;
    int src = ei[w];
    int dst = ei[E + w];
    if ((unsigned)src >= (unsigned)N || (unsigned)dst >= (unsigned)N) return;  // safety
    float s = g_inv[r * N + dst];

    const float4* xr = (const float4*)(x + (size_t)src * CH);
    float4 v = xr[lane];
    float* h = g_h + (size_t)dst * CH + lane * 4;
    atomicAdd(h + 0, v.x * s);
    atomicAdd(h + 1, v.y * s);
    atomicAdd(h + 2, v.z * s);
    atomicAdd(h + 3, v.w * s);
}

// ---------------- GEMM: out (+)= A[N,128] @ B[128,128]  ----------------
// use_gh: read A from the __device__ global g_h (device-side symbol access).
// mode 0: out = A@B + bias (root pass).  mode 1: out += A@B (relation pass).
__global__ __launch_bounds__(256) void gemm_kernel(
    const float* __restrict__ Ain, const float* __restrict__ B,
    const float* __restrict__ bias, float* __restrict__ out,
    int N, int mode, int use_gh) {
    __shared__ __align__(16) float As[32 * 128];  // [k][m] (transposed)
    __shared__ __align__(16) float Bs[32 * 128];  // [k][n]

    const int m0  = blockIdx.x * 128;
    const int tid = threadIdx.x;
    const int tm  = tid >> 4;   // 0..15
    const int tn  = tid & 15;   // 0..15

    const float* A = use_gh ? (const float*)g_h : Ain;
    const float4* A4 = (const float4*)A;

    float acc[8][8];
#pragma unroll
    for (int i = 0; i < 8; i++)
#pragma unroll
        for (int j = 0; j < 8; j++) acc[i][j] = 0.0f;

    for (int kt = 0; kt < 4; ++kt) {
        // load A tile transposed into As[k][m]
#pragma unroll
        for (int it = 0; it < 4; ++it) {
            int f   = tid + it * 256;   // 0..1023
            int row = f >> 3;
            int kq  = f & 7;
            float4 v = make_float4(0.f, 0.f, 0.f, 0.f);
            int gr = m0 + row;
            if (gr < N) v = A4[(size_t)gr * 32 + kt * 8 + kq];
            As[(kq * 4 + 0) * 128 + row] = v.x;
            As[(kq * 4 + 1) * 128 + row] = v.y;
            As[(kq * 4 + 2) * 128 + row] = v.z;
            As[(kq * 4 + 3) * 128 + row] = v.w;
        }
        // weight tile is k-major already: direct copy
        const float4* Bsrc = (const float4*)(B + kt * 32 * 128);
        float4* Bs4w = (float4*)Bs;
#pragma unroll
        for (int it = 0; it < 4; ++it) Bs4w[tid + it * 256] = Bsrc[tid + it * 256];
        __syncthreads();

        const float4* As4 = (const float4*)As;
        const float4* Bs4 = (const float4*)Bs;
#pragma unroll
        for (int k = 0; k < 32; k++) {
            float4 a0 = As4[k * 32 + tm * 2];
            float4 a1 = As4[k * 32 + tm * 2 + 1];
            float4 b0 = Bs4[k * 32 + tn * 2];
            float4 b1 = Bs4[k * 32 + tn * 2 + 1];
            float av[8] = {a0.x, a0.y, a0.z, a0.w, a1.x, a1.y, a1.z, a1.w};
            float bv[8] = {b0.x, b0.y, b0.z, b0.w, b1.x, b1.y, b1.z, b1.w};
#pragma unroll
            for (int i = 0; i < 8; i++)
#pragma unroll
                for (int j = 0; j < 8; j++)
                    acc[i][j] = fmaf(av[i], bv[j], acc[i][j]);
        }
        __syncthreads();
    }

    float bb[8];
    if (mode == 0) {
#pragma unroll
        for (int j = 0; j < 8; j++) bb[j] = bias[tn * 8 + j];
    }

#pragma unroll
    for (int i = 0; i < 8; i++) {
        int gr = m0 + tm * 8 + i;
        if (gr >= N) continue;
        float* dst = out + (size_t)gr * CH + tn * 8;
        float4* d4 = (float4*)dst;
        if (mode == 0) {
            d4[0] = make_float4(acc[i][0] + bb[0], acc[i][1] + bb[1],
                                acc[i][2] + bb[2], acc[i][3] + bb[3]);
            d4[1] = make_float4(acc[i][4] + bb[4], acc[i][5] + bb[5],
                                acc[i][6] + bb[6], acc[i][7] + bb[7]);
        } else {
            float4 o0 = d4[0], o1 = d4[1];
            d4[0] = make_float4(o0.x + acc[i][0], o0.y + acc[i][1],
                                o0.z + acc[i][2], o0.w + acc[i][3]);
            d4[1] = make_float4(o1.x + acc[i][4], o1.y + acc[i][5],
                                o1.z + acc[i][6], o1.w + acc[i][7]);
        }
    }
}

// ---------------- launch ----------------
extern "C" void kernel_launch(void* const* d_in, const int* in_sizes, int n_in,
                              void* d_out, int out_size) {
    const float* x      = (const float*)d_in[0];
    const int*   ei     = (const int*)d_in[1];    // int32 (JAX x64 off)
    const int*   et     = (const int*)d_in[2];    // int32
    const float* weight = (const float*)d_in[3];
    const float* root   = (const float*)d_in[4];
    const float* bias   = (const float*)d_in[5];
    float*       out    = (float*)d_out;

    int N  = in_sizes[0] / CH;       // 100000
    int E  = in_sizes[2];            // 1600000
    int RN = NREL * N;
    int gemm_blocks = (N + 127) / 128;
    int agg_blocks  = (int)(((size_t)E * 32 + 255) / 256);

    zero_cnt_kernel<<<(RN + 255) / 256, 256>>>(RN);
    count_kernel<<<(E + 255) / 256, 256>>>(ei, et, E, N);
    inv_kernel<<<(RN + 255) / 256, 256>>>(RN);

    // root pass: out = x @ root + bias
    gemm_kernel<<<gemm_blocks, 256>>>(x, root, bias, out, N, 0, 0);

    // relation passes: h = mean-aggregate; out += h @ W_r
    for (int r = 0; r < NREL; ++r) {
        int n4 = N * CH / 4;
        zero_h_kernel<<<(n4 + 255) / 256, 256>>>(n4);
        aggregate_kernel<<<agg_blocks, 256>>>(ei, et, x, r, E, N);
        gemm_kernel<<<gemm_blocks, 256>>>(nullptr, weight + (size_t)r * CH * CH,
                                          nullptr, out, N, 1, 1);
    }
}

// round 10
// speedup vs baseline: 1.5085x; 1.5085x over previous
#include <cuda_runtime.h>
#include <cstdint>

#define CH    128
#define NREL  8
#define MAXN  100000
#define MAXE  1600000
#define RNMAX (NREL * MAXN)
#define CHUNK 4096
#define NCHUNKS ((RNMAX + CHUNK - 1) / CHUNK)

// Static scratch (~67MB total)
__device__ __align__(16) float g_h[(size_t)MAXN * CH]; // 51.2MB per-relation mean
__device__ int g_cnt[RNMAX];          // histogram per (rel,dst)
__device__ int g_start[RNMAX + 1];    // CSR segment starts (exclusive scan)
__device__ int g_pos[RNMAX];          // insert cursors
__device__ int g_sorted[MAXE];        // src node per edge, sorted by (rel,dst)
__device__ int g_blocksum[NCHUNKS];

// ---------------- packed fp32x2 helpers (Blackwell FFMA2) ----------------
__device__ __forceinline__ unsigned long long pack_dup(float a) {
    unsigned long long r;
    asm("mov.b64 %0, {%1, %1};" : "=l"(r) : "f"(a));
    return r;
}
__device__ __forceinline__ void fma2(unsigned long long& d, unsigned long long a,
                                     unsigned long long b) {
    asm("fma.rn.f32x2 %0, %1, %2, %0;" : "+l"(d) : "l"(a), "l"(b));
}
__device__ __forceinline__ float2 unpack2(unsigned long long v) {
    float2 f;
    asm("mov.b64 {%0, %1}, %2;" : "=f"(f.x), "=f"(f.y) : "l"(v));
    return f;
}

// ---------------- CSR build ----------------
__global__ void zero_cnt_kernel(int n) {
    int i = blockIdx.x * blockDim.x + threadIdx.x;
    if (i < n) g_cnt[i] = 0;
}

__global__ void hist_kernel(const int* __restrict__ ei,
                            const int* __restrict__ et, int E, int N) {
    int e = blockIdx.x * blockDim.x + threadIdx.x;
    if (e >= E) return;
    int dst = ei[E + e];
    int t   = et[e];
    int src = ei[e];
    if ((unsigned)dst >= (unsigned)N || (unsigned)t >= NREL ||
        (unsigned)src >= (unsigned)N) return;
    atomicAdd(&g_cnt[t * N + dst], 1);
}

// S1: per-chunk totals
__global__ void scan_blocksum_kernel(int n) {
    __shared__ int sdata[256];
    int b = blockIdx.x, t = threadIdx.x;
    int base = b * CHUNK;
    int sum = 0;
    for (int i = t; i < CHUNK; i += 256) {
        int idx = base + i;
        sum += (idx < n) ? g_cnt[idx] : 0;
    }
    sdata[t] = sum;
    __syncthreads();
    for (int s = 128; s > 0; s >>= 1) {
        if (t < s) sdata[t] += sdata[t + s];
        __syncthreads();
    }
    if (t == 0) g_blocksum[b] = sdata[0];
}

// S2: exclusive scan of chunk totals (+ total into g_start[n])
__global__ void scan_offsets_kernel(int nb, int n) {
    if (threadIdx.x == 0 && blockIdx.x == 0) {
        int acc = 0;
        for (int i = 0; i < nb; i++) {
            int v = g_blocksum[i];
            g_blocksum[i] = acc;
            acc += v;
        }
        g_start[n] = acc;
    }
}

// S3: per-chunk exclusive scan -> g_start / g_pos
__global__ void scan_chunk_kernel(int n) {
    __shared__ int sdata[256];
    int b = blockIdx.x, t = threadIdx.x;
    int base = b * CHUNK + t * 16;
    int local[16];
    int sum = 0;
#pragma unroll
    for (int i = 0; i < 16; i++) {
        int idx = base + i;
        int v = (idx < n) ? g_cnt[idx] : 0;
        local[i] = sum;
        sum += v;
    }
    sdata[t] = sum;
    __syncthreads();
    if (t == 0) {
        int acc = 0;
        for (int i = 0; i < 256; i++) { int v = sdata[i]; sdata[i] = acc; acc += v; }
    }
    __syncthreads();
    int off = g_blocksum[b] + sdata[t];
#pragma unroll
    for (int i = 0; i < 16; i++) {
        int idx = base + i;
        if (idx < n) {
            int v = off + local[i];
            g_start[idx] = v;
            g_pos[idx]   = v;
        }
    }
}

__global__ void scatter_edges_kernel(const int* __restrict__ ei,
                                     const int* __restrict__ et, int E, int N) {
    int e = blockIdx.x * blockDim.x + threadIdx.x;
    if (e >= E) return;
    int src = ei[e];
    int dst = ei[E + e];
    int t   = et[e];
    if ((unsigned)dst >= (unsigned)N || (unsigned)t >= NREL ||
        (unsigned)src >= (unsigned)N) return;
    int pos = atomicAdd(&g_pos[t * N + dst], 1);
    g_sorted[pos] = src;
}

// ---------------- atomic-free mean aggregation for relation r ----------------
// One warp per dst node; lane l owns floats [4l,4l+4). Writes g_h (incl. zeros).
__global__ void aggregate_csr_kernel(const float* __restrict__ x, int r, int N) {
    int node = (int)((blockIdx.x * (size_t)blockDim.x + threadIdx.x) >> 5);
    int lane = threadIdx.x & 31;
    if (node >= N) return;
    int seg   = r * N + node;
    int begin = g_start[seg];
    int end   = g_start[seg + 1];

    const float4* x4 = (const float4*)x;
    float4 acc = make_float4(0.f, 0.f, 0.f, 0.f);
    for (int e = begin; e < end; e++) {
        int src = g_sorted[e];
        float4 v = x4[(size_t)src * 32 + lane];
        acc.x += v.x; acc.y += v.y; acc.z += v.z; acc.w += v.w;
    }
    float inv = (end > begin) ? 1.0f / (float)(end - begin) : 0.0f;
    ((float4*)g_h)[(size_t)node * 32 + lane] =
        make_float4(acc.x * inv, acc.y * inv, acc.z * inv, acc.w * inv);
}

// ---------------- GEMM: out (+)= A[N,128] @ B[128,128], packed f32x2 ----------------
// use_gh: A = g_h (device-side symbol). mode 0: out = A@B + bias; mode 1: out += A@B.
__global__ __launch_bounds__(256) void gemm_kernel(
    const float* __restrict__ Ain, const float* __restrict__ B,
    const float* __restrict__ bias, float* __restrict__ out,
    int N, int mode, int use_gh) {
    __shared__ __align__(16) float As[32 * 128];  // [k][m]
    __shared__ __align__(16) float Bs[32 * 128];  // [k][n]

    const int m0  = blockIdx.x * 128;
    const int tid = threadIdx.x;
    const int tm  = tid >> 4;
    const int tn  = tid & 15;

    const float* A = use_gh ? (const float*)g_h : Ain;
    const float4* A4 = (const float4*)A;

    unsigned long long acc[8][4];
#pragma unroll
    for (int i = 0; i < 8; i++)
#pragma unroll
        for (int j = 0; j < 4; j++) acc[i][j] = 0ull;

    for (int kt = 0; kt < 4; ++kt) {
#pragma unroll
        for (int it = 0; it < 4; ++it) {
            int f   = tid + it * 256;
            int row = f >> 3;
            int kq  = f & 7;
            float4 v = make_float4(0.f, 0.f, 0.f, 0.f);
            int gr = m0 + row;
            if (gr < N) v = A4[(size_t)gr * 32 + kt * 8 + kq];
            As[(kq * 4 + 0) * 128 + row] = v.x;
            As[(kq * 4 + 1) * 128 + row] = v.y;
            As[(kq * 4 + 2) * 128 + row] = v.z;
            As[(kq * 4 + 3) * 128 + row] = v.w;
        }
        const float4* Bsrc = (const float4*)(B + kt * 32 * 128);
        float4* Bs4w = (float4*)Bs;
#pragma unroll
        for (int it = 0; it < 4; ++it) Bs4w[tid + it * 256] = Bsrc[tid + it * 256];
        __syncthreads();

        const float4* As4     = (const float4*)As;
        const ulonglong2* Bs2 = (const ulonglong2*)Bs;
#pragma unroll
        for (int k = 0; k < 32; k++) {
            float4 a0 = As4[k * 32 + tm * 2];
            float4 a1 = As4[k * 32 + tm * 2 + 1];
            ulonglong2 b0 = Bs2[k * 32 + tn * 2];
            ulonglong2 b1 = Bs2[k * 32 + tn * 2 + 1];
            unsigned long long bb[4] = {b0.x, b0.y, b1.x, b1.y};
            float av[8] = {a0.x, a0.y, a0.z, a0.w, a1.x, a1.y, a1.z, a1.w};
#pragma unroll
            for (int i = 0; i < 8; i++) {
                unsigned long long aa = pack_dup(av[i]);
#pragma unroll
                for (int j = 0; j < 4; j++) fma2(acc[i][j], aa, bb[j]);
            }
        }
        __syncthreads();
    }

    float bb[8];
    if (mode == 0) {
#pragma unroll
        for (int j = 0; j < 8; j++) bb[j] = bias[tn * 8 + j];
    }

#pragma unroll
    for (int i = 0; i < 8; i++) {
        int gr = m0 + tm * 8 + i;
        if (gr >= N) continue;
        float vals[8];
#pragma unroll
        for (int j = 0; j < 4; j++) {
            float2 p = unpack2(acc[i][j]);
            vals[2 * j]     = p.x;
            vals[2 * j + 1] = p.y;
        }
        float4* d4 = (float4*)(out + (size_t)gr * CH + tn * 8);
        if (mode == 0) {
            d4[0] = make_float4(vals[0] + bb[0], vals[1] + bb[1],
                                vals[2] + bb[2], vals[3] + bb[3]);
            d4[1] = make_float4(vals[4] + bb[4], vals[5] + bb[5],
                                vals[6] + bb[6], vals[7] + bb[7]);
        } else {
            float4 o0 = d4[0], o1 = d4[1];
            d4[0] = make_float4(o0.x + vals[0], o0.y + vals[1],
                                o0.z + vals[2], o0.w + vals[3]);
            d4[1] = make_float4(o1.x + vals[4], o1.y + vals[5],
                                o1.z + vals[6], o1.w + vals[7]);
        }
    }
}

// ---------------- launch ----------------
extern "C" void kernel_launch(void* const* d_in, const int* in_sizes, int n_in,
                              void* d_out, int out_size) {
    const float* x      = (const float*)d_in[0];
    const int*   ei     = (const int*)d_in[1];    // int32 (JAX x64 off)
    const int*   et     = (const int*)d_in[2];
    const float* weight = (const float*)d_in[3];
    const float* root   = (const float*)d_in[4];
    const float* bias   = (const float*)d_in[5];
    float*       out    = (float*)d_out;

    int N  = in_sizes[0] / CH;       // 100000
    int E  = in_sizes[2];            // 1600000
    int RN = NREL * N;
    int nb = (RN + CHUNK - 1) / CHUNK;
    int gemm_blocks = (N + 127) / 128;
    int agg_blocks  = (int)(((size_t)N * 32 + 255) / 256);

    // CSR build: hist -> scan -> scatter
    zero_cnt_kernel<<<(RN + 255) / 256, 256>>>(RN);
    hist_kernel<<<(E + 255) / 256, 256>>>(ei, et, E, N);
    scan_blocksum_kernel<<<nb, 256>>>(RN);
    scan_offsets_kernel<<<1, 32>>>(nb, RN);
    scan_chunk_kernel<<<nb, 256>>>(RN);
    scatter_edges_kernel<<<(E + 255) / 256, 256>>>(ei, et, E, N);

    // root pass: out = x @ root + bias
    gemm_kernel<<<gemm_blocks, 256>>>(x, root, bias, out, N, 0, 0);

    // relation passes: h = mean-aggregate (atomic-free); out += h @ W_r
    for (int r = 0; r < NREL; ++r) {
        aggregate_csr_kernel<<<agg_blocks, 256>>>(x, r, N);
        gemm_kernel<<<gemm_blocks, 256>>>(nullptr, weight + (size_t)r * CH * CH,
                                          nullptr, out, N, 1, 1);
    }
}

// round 11
// speedup vs baseline: 2.0125x; 1.3341x over previous
#include <cuda_runtime.h>
#include <cstdint>

#define CH    128
#define NREL  8
#define NSLOT 9                  // 8 relations + root(x) slot
#define KDIM  (NSLOT * CH)       // 1152
#define MAXN  100000
#define MAXE  1600000
#define RNMAX (NREL * MAXN)
#define CHUNK 4096
#define NCHUNKS ((RNMAX + CHUNK - 1) / CHUNK)

// Static scratch (~490MB total; large statics are fine — R4-7 traps were bad indices)
__device__ __align__(16) float g_xw[(size_t)MAXN * KDIM];  // 460.8MB A matrix [N,9,128]
__device__ int g_cnt[RNMAX];
__device__ int g_start[RNMAX + 1];
__device__ int g_pos[RNMAX];
__device__ int g_sorted[MAXE];
__device__ int g_blocksum[NCHUNKS];

// ---------------- packed fp32x2 helpers (Blackwell FFMA2) ----------------
__device__ __forceinline__ unsigned long long pack_dup(float a) {
    unsigned long long r;
    asm("mov.b64 %0, {%1, %1};" : "=l"(r) : "f"(a));
    return r;
}
__device__ __forceinline__ void fma2(unsigned long long& d, unsigned long long a,
                                     unsigned long long b) {
    asm("fma.rn.f32x2 %0, %1, %2, %0;" : "+l"(d) : "l"(a), "l"(b));
}
__device__ __forceinline__ float2 unpack2(unsigned long long v) {
    float2 f;
    asm("mov.b64 {%0, %1}, %2;" : "=f"(f.x), "=f"(f.y) : "l"(v));
    return f;
}

// ---------------- CSR build ----------------
__global__ void zero_cnt_kernel(int n) {
    int i = blockIdx.x * blockDim.x + threadIdx.x;
    if (i < n) g_cnt[i] = 0;
}

__global__ void hist_kernel(const int* __restrict__ ei,
                            const int* __restrict__ et, int E, int N) {
    int e = blockIdx.x * blockDim.x + threadIdx.x;
    if (e >= E) return;
    int dst = ei[E + e];
    int t   = et[e];
    int src = ei[e];
    if ((unsigned)dst >= (unsigned)N || (unsigned)t >= NREL ||
        (unsigned)src >= (unsigned)N) return;
    atomicAdd(&g_cnt[t * N + dst], 1);
}

__global__ void scan_blocksum_kernel(int n) {
    __shared__ int sdata[256];
    int b = blockIdx.x, t = threadIdx.x;
    int base = b * CHUNK;
    int sum = 0;
    for (int i = t; i < CHUNK; i += 256) {
        int idx = base + i;
        sum += (idx < n) ? g_cnt[idx] : 0;
    }
    sdata[t] = sum;
    __syncthreads();
    for (int s = 128; s > 0; s >>= 1) {
        if (t < s) sdata[t] += sdata[t + s];
        __syncthreads();
    }
    if (t == 0) g_blocksum[b] = sdata[0];
}

__global__ void scan_offsets_kernel(int nb, int n) {
    if (threadIdx.x == 0 && blockIdx.x == 0) {
        int acc = 0;
        for (int i = 0; i < nb; i++) {
            int v = g_blocksum[i];
            g_blocksum[i] = acc;
            acc += v;
        }
        g_start[n] = acc;
    }
}

__global__ void scan_chunk_kernel(int n) {
    __shared__ int sdata[256];
    int b = blockIdx.x, t = threadIdx.x;
    int base = b * CHUNK + t * 16;
    int local[16];
    int sum = 0;
#pragma unroll
    for (int i = 0; i < 16; i++) {
        int idx = base + i;
        int v = (idx < n) ? g_cnt[idx] : 0;
        local[i] = sum;
        sum += v;
    }
    sdata[t] = sum;
    __syncthreads();
    if (t == 0) {
        int acc = 0;
        for (int i = 0; i < 256; i++) { int v = sdata[i]; sdata[i] = acc; acc += v; }
    }
    __syncthreads();
    int off = g_blocksum[b] + sdata[t];
#pragma unroll
    for (int i = 0; i < 16; i++) {
        int idx = base + i;
        if (idx < n) {
            int v = off + local[i];
            g_start[idx] = v;
            g_pos[idx]   = v;
        }
    }
}

__global__ void scatter_edges_kernel(const int* __restrict__ ei,
                                     const int* __restrict__ et, int E, int N) {
    int e = blockIdx.x * blockDim.x + threadIdx.x;
    if (e >= E) return;
    int src = ei[e];
    int dst = ei[E + e];
    int t   = et[e];
    if ((unsigned)dst >= (unsigned)N || (unsigned)t >= NREL ||
        (unsigned)src >= (unsigned)N) return;
    int pos = atomicAdd(&g_pos[t * N + dst], 1);
    g_sorted[pos] = src;
}

// ---------------- fused aggregation: build A = [h_0..h_7 | x] per node ----------------
// One warp per (slot, node). slot<8: mean over CSR segment; slot==8: copy x row.
__global__ void aggregate_all_kernel(const float* __restrict__ x, int N) {
    size_t gw = ((size_t)blockIdx.x * blockDim.x + threadIdx.x) >> 5;
    int lane = threadIdx.x & 31;
    size_t total = (size_t)N * NSLOT;
    if (gw >= total) return;
    int r    = (int)(gw / N);          // 0..8
    int node = (int)(gw - (size_t)r * N);

    const float4* x4 = (const float4*)x;
    float4 res;
    if (r == NREL) {
        res = x4[(size_t)node * 32 + lane];
    } else {
        int seg   = r * N + node;      // == gw
        int begin = g_start[seg];
        int end   = g_start[seg + 1];
        float4 acc = make_float4(0.f, 0.f, 0.f, 0.f);
        for (int e = begin; e < end; e++) {
            int src = g_sorted[e];
            float4 v = x4[(size_t)src * 32 + lane];
            acc.x += v.x; acc.y += v.y; acc.z += v.z; acc.w += v.w;
        }
        float inv = (end > begin) ? 1.0f / (float)(end - begin) : 0.0f;
        res = make_float4(acc.x * inv, acc.y * inv, acc.z * inv, acc.w * inv);
    }
    ((float4*)g_xw)[((size_t)node * NSLOT + r) * 32 + lane] = res;
}

// ---------------- single GEMM: out = g_xw[N,1152] @ Bcat[1152,128] + bias ----------------
// Bcat rows 0..1023 = weight (contiguous [8,128,128] k-major), rows 1024..1151 = root.
__global__ __launch_bounds__(256) void gemm_kernel(
    const float* __restrict__ weight, const float* __restrict__ root,
    const float* __restrict__ bias, float* __restrict__ out, int N) {
    __shared__ __align__(16) float As[32 * 128];  // [k][m]
    __shared__ __align__(16) float Bs[32 * 128];  // [k][n]

    const int m0  = blockIdx.x * 128;
    const int tid = threadIdx.x;
    const int tm  = tid >> 4;
    const int tn  = tid & 15;

    const float4* A4 = (const float4*)g_xw;   // row stride 288 float4

    unsigned long long acc[8][4];
#pragma unroll
    for (int i = 0; i < 8; i++)
#pragma unroll
        for (int j = 0; j < 4; j++) acc[i][j] = 0ull;

    for (int kt = 0; kt < 36; ++kt) {
        // load A tile transposed into As[k][m]
#pragma unroll
        for (int it = 0; it < 4; ++it) {
            int f   = tid + it * 256;
            int row = f >> 3;
            int kq  = f & 7;
            float4 v = make_float4(0.f, 0.f, 0.f, 0.f);
            int gr = m0 + row;
            if (gr < N) v = A4[(size_t)gr * 288 + kt * 8 + kq];
            As[(kq * 4 + 0) * 128 + row] = v.x;
            As[(kq * 4 + 1) * 128 + row] = v.y;
            As[(kq * 4 + 2) * 128 + row] = v.z;
            As[(kq * 4 + 3) * 128 + row] = v.w;
        }
        // B tile: k-major concatenation of weight then root
        const float* Bbase = (kt < 32) ? (weight + (size_t)kt * 32 * 128)
                                       : (root + (size_t)(kt - 32) * 32 * 128);
        const float4* Bsrc = (const float4*)Bbase;
        float4* Bs4w = (float4*)Bs;
#pragma unroll
        for (int it = 0; it < 4; ++it) Bs4w[tid + it * 256] = Bsrc[tid + it * 256];
        __syncthreads();

        const float4* As4     = (const float4*)As;
        const ulonglong2* Bs2 = (const ulonglong2*)Bs;
#pragma unroll
        for (int k = 0; k < 32; k++) {
            float4 a0 = As4[k * 32 + tm * 2];
            float4 a1 = As4[k * 32 + tm * 2 + 1];
            ulonglong2 b0 = Bs2[k * 32 + tn * 2];
            ulonglong2 b1 = Bs2[k * 32 + tn * 2 + 1];
            unsigned long long bb[4] = {b0.x, b0.y, b1.x, b1.y};
            float av[8] = {a0.x, a0.y, a0.z, a0.w, a1.x, a1.y, a1.z, a1.w};
#pragma unroll
            for (int i = 0; i < 8; i++) {
                unsigned long long aa = pack_dup(av[i]);
#pragma unroll
                for (int j = 0; j < 4; j++) fma2(acc[i][j], aa, bb[j]);
            }
        }
        __syncthreads();
    }

    float bb[8];
#pragma unroll
    for (int j = 0; j < 8; j++) bb[j] = bias[tn * 8 + j];

#pragma unroll
    for (int i = 0; i < 8; i++) {
        int gr = m0 + tm * 8 + i;
        if (gr >= N) continue;
        float vals[8];
#pragma unroll
        for (int j = 0; j < 4; j++) {
            float2 p = unpack2(acc[i][j]);
            vals[2 * j]     = p.x;
            vals[2 * j + 1] = p.y;
        }
        float4* d4 = (float4*)(out + (size_t)gr * CH + tn * 8);
        d4[0] = make_float4(vals[0] + bb[0], vals[1] + bb[1],
                            vals[2] + bb[2], vals[3] + bb[3]);
        d4[1] = make_float4(vals[4] + bb[4], vals[5] + bb[5],
                            vals[6] + bb[6], vals[7] + bb[7]);
    }
}

// ---------------- launch ----------------
extern "C" void kernel_launch(void* const* d_in, const int* in_sizes, int n_in,
                              void* d_out, int out_size) {
    const float* x      = (const float*)d_in[0];
    const int*   ei     = (const int*)d_in[1];    // int32 (JAX x64 off)
    const int*   et     = (const int*)d_in[2];
    const float* weight = (const float*)d_in[3];
    const float* root   = (const float*)d_in[4];
    const float* bias   = (const float*)d_in[5];
    float*       out    = (float*)d_out;

    int N  = in_sizes[0] / CH;       // 100000
    int E  = in_sizes[2];            // 1600000
    int RN = NREL * N;
    int nb = (RN + CHUNK - 1) / CHUNK;
    int gemm_blocks = (N + 127) / 128;
    size_t agg_warps = (size_t)N * NSLOT;
    int agg_blocks = (int)((agg_warps * 32 + 255) / 256);

    // CSR build
    zero_cnt_kernel<<<(RN + 255) / 256, 256>>>(RN);
    hist_kernel<<<(E + 255) / 256, 256>>>(ei, et, E, N);
    scan_blocksum_kernel<<<nb, 256>>>(RN);
    scan_offsets_kernel<<<1, 32>>>(nb, RN);
    scan_chunk_kernel<<<nb, 256>>>(RN);
    scatter_edges_kernel<<<(E + 255) / 256, 256>>>(ei, et, E, N);

    // fused aggregation (8 relation means + x copy) -> g_xw [N, 1152]
    aggregate_all_kernel<<<agg_blocks, 256>>>(x, N);

    // single fused GEMM: out = g_xw @ [W_0..W_7; root] + bias
    gemm_kernel<<<gemm_blocks, 256>>>(weight, root, bias, out, N);
}

// round 12
// speedup vs baseline: 2.7088x; 1.3460x over previous
#include <cuda_runtime.h>
#include <cuda_bf16.h>
#include <cstdint>

#define CH    128
#define NREL  8
#define NSLOT 9                  // 8 relations + root(x) slot
#define KDIM  (NSLOT * CH)       // 1152
#define MAXN  100000
#define MAXE  1600000
#define RNMAX (NREL * MAXN)
#define CHUNK 4096
#define NCHUNKS ((RNMAX + CHUNK - 1) / CHUNK)

// Static scratch
__device__ __align__(16) float g_xw[(size_t)MAXN * KDIM];  // 460.8MB A matrix [N,9,128]
__device__ int g_cnt[RNMAX];
__device__ int g_start[RNMAX + 1];
__device__ int g_pos[RNMAX];
__device__ int g_sorted[MAXE];
__device__ int g_blocksum[NCHUNKS];

// ---------------- CSR build ----------------
__global__ void zero_cnt_kernel(int n) {
    int i = blockIdx.x * blockDim.x + threadIdx.x;
    if (i < n) g_cnt[i] = 0;
}

__global__ void hist_kernel(const int* __restrict__ ei,
                            const int* __restrict__ et, int E, int N) {
    int e = blockIdx.x * blockDim.x + threadIdx.x;
    if (e >= E) return;
    int dst = ei[E + e];
    int t   = et[e];
    int src = ei[e];
    if ((unsigned)dst >= (unsigned)N || (unsigned)t >= NREL ||
        (unsigned)src >= (unsigned)N) return;
    atomicAdd(&g_cnt[t * N + dst], 1);
}

__global__ void scan_blocksum_kernel(int n) {
    __shared__ int sdata[256];
    int b = blockIdx.x, t = threadIdx.x;
    int base = b * CHUNK;
    int sum = 0;
    for (int i = t; i < CHUNK; i += 256) {
        int idx = base + i;
        sum += (idx < n) ? g_cnt[idx] : 0;
    }
    sdata[t] = sum;
    __syncthreads();
    for (int s = 128; s > 0; s >>= 1) {
        if (t < s) sdata[t] += sdata[t + s];
        __syncthreads();
    }
    if (t == 0) g_blocksum[b] = sdata[0];
}

__global__ void scan_offsets_kernel(int nb, int n) {
    if (threadIdx.x == 0 && blockIdx.x == 0) {
        int acc = 0;
        for (int i = 0; i < nb; i++) {
            int v = g_blocksum[i];
            g_blocksum[i] = acc;
            acc += v;
        }
        g_start[n] = acc;
    }
}

__global__ void scan_chunk_kernel(int n) {
    __shared__ int sdata[256];
    int b = blockIdx.x, t = threadIdx.x;
    int base = b * CHUNK + t * 16;
    int local[16];
    int sum = 0;
#pragma unroll
    for (int i = 0; i < 16; i++) {
        int idx = base + i;
        int v = (idx < n) ? g_cnt[idx] : 0;
        local[i] = sum;
        sum += v;
    }
    sdata[t] = sum;
    __syncthreads();
    if (t == 0) {
        int acc = 0;
        for (int i = 0; i < 256; i++) { int v = sdata[i]; sdata[i] = acc; acc += v; }
    }
    __syncthreads();
    int off = g_blocksum[b] + sdata[t];
#pragma unroll
    for (int i = 0; i < 16; i++) {
        int idx = base + i;
        if (idx < n) {
            int v = off + local[i];
            g_start[idx] = v;
            g_pos[idx]   = v;
        }
    }
}

__global__ void scatter_edges_kernel(const int* __restrict__ ei,
                                     const int* __restrict__ et, int E, int N) {
    int e = blockIdx.x * blockDim.x + threadIdx.x;
    if (e >= E) return;
    int src = ei[e];
    int dst = ei[E + e];
    int t   = et[e];
    if ((unsigned)dst >= (unsigned)N || (unsigned)t >= NREL ||
        (unsigned)src >= (unsigned)N) return;
    int pos = atomicAdd(&g_pos[t * N + dst], 1);
    g_sorted[pos] = src;
}

// ---------------- fused aggregation: build A = [h_0..h_7 | x] per node ----------------
__global__ void aggregate_all_kernel(const float* __restrict__ x, int N) {
    size_t gw = ((size_t)blockIdx.x * blockDim.x + threadIdx.x) >> 5;
    int lane = threadIdx.x & 31;
    size_t total = (size_t)N * NSLOT;
    if (gw >= total) return;
    int r    = (int)(gw / N);          // 0..8
    int node = (int)(gw - (size_t)r * N);

    const float4* x4 = (const float4*)x;
    float4 res;
    if (r == NREL) {
        res = x4[(size_t)node * 32 + lane];
    } else {
        int seg   = r * N + node;
        int begin = g_start[seg];
        int end   = g_start[seg + 1];
        float4 acc = make_float4(0.f, 0.f, 0.f, 0.f);
        for (int e = begin; e < end; e++) {
            int src = g_sorted[e];
            float4 v = x4[(size_t)src * 32 + lane];
            acc.x += v.x; acc.y += v.y; acc.z += v.z; acc.w += v.w;
        }
        float inv = (end > begin) ? 1.0f / (float)(end - begin) : 0.0f;
        res = make_float4(acc.x * inv, acc.y * inv, acc.z * inv, acc.w * inv);
    }
    ((float4*)g_xw)[((size_t)node * NSLOT + r) * 32 + lane] = res;
}

// ---------------- tensor-core GEMM: out = g_xw[N,1152] @ Bcat[1152,128] + bias --------
// bf16 2-term split (hi/lo): out = Ah*Bh + Ah*Bl + Al*Bh  (fp32 accum via mma.sync)
#define AS_STRIDE 40    // halves per A smem row (pad 32->40, conflict-free ldmatrix)
#define BS_STRIDE 136   // halves per B smem row (pad 128->136)

__device__ __forceinline__ uint32_t smem_u32(const void* p) {
    uint32_t a;
    asm("{ .reg .u64 t; cvta.to.shared.u64 t, %1; cvt.u32.u64 %0, t; }"
        : "=r"(a) : "l"(p));
    return a;
}

__device__ __forceinline__ void split2(float v0, float v1,
                                       uint32_t& hi, uint32_t& lo) {
    __nv_bfloat16 h0 = __float2bfloat16(v0);
    __nv_bfloat16 h1 = __float2bfloat16(v1);
    __nv_bfloat16 l0 = __float2bfloat16(v0 - __bfloat162float(h0));
    __nv_bfloat16 l1 = __float2bfloat16(v1 - __bfloat162float(h1));
    hi = (uint32_t)__bfloat16_as_ushort(h0) | ((uint32_t)__bfloat16_as_ushort(h1) << 16);
    lo = (uint32_t)__bfloat16_as_ushort(l0) | ((uint32_t)__bfloat16_as_ushort(l1) << 16);
}

#define LDSM_X4(r, addr)                                                        \
    asm volatile("ldmatrix.sync.aligned.m8n8.x4.shared.b16 {%0,%1,%2,%3},[%4];" \
                 : "=r"((r)[0]), "=r"((r)[1]), "=r"((r)[2]), "=r"((r)[3])        \
                 : "r"(addr))
#define LDSM_X4T(r, addr)                                                             \
    asm volatile("ldmatrix.sync.aligned.m8n8.x4.trans.shared.b16 {%0,%1,%2,%3},[%4];" \
                 : "=r"((r)[0]), "=r"((r)[1]), "=r"((r)[2]), "=r"((r)[3])              \
                 : "r"(addr))
#define MMA_BF16(d, a, b0, b1)                                              \
    asm volatile("mma.sync.aligned.m16n8k16.row.col.f32.bf16.bf16.f32 "     \
                 "{%0,%1,%2,%3},{%4,%5,%6,%7},{%8,%9},{%0,%1,%2,%3};"       \
                 : "+f"((d)[0]), "+f"((d)[1]), "+f"((d)[2]), "+f"((d)[3])    \
                 : "r"((a)[0]), "r"((a)[1]), "r"((a)[2]), "r"((a)[3]),       \
                   "r"(b0), "r"(b1))

__global__ __launch_bounds__(256, 1) void gemm_kernel(
    const float* __restrict__ weight, const float* __restrict__ root,
    const float* __restrict__ bias, float* __restrict__ out, int N) {
    __shared__ __align__(16) unsigned short AsH[128 * AS_STRIDE];
    __shared__ __align__(16) unsigned short AsL[128 * AS_STRIDE];
    __shared__ __align__(16) unsigned short BsH[32 * BS_STRIDE];
    __shared__ __align__(16) unsigned short BsL[32 * BS_STRIDE];

    const int tid  = threadIdx.x;
    const int lane = tid & 31;
    const int wid  = tid >> 5;
    const int m0   = blockIdx.x * 128;
    const int wm   = (wid >> 1) * 32;   // warp m-offset (4 warps x 32 rows)
    const int wn   = (wid & 1) * 64;    // warp n-offset (2 warps x 64 cols)

    const float4* A4 = (const float4*)g_xw;   // row stride 288 float4

    float acc[2][8][4];
#pragma unroll
    for (int i = 0; i < 2; i++)
#pragma unroll
        for (int j = 0; j < 8; j++)
#pragma unroll
            for (int q = 0; q < 4; q++) acc[i][j][q] = 0.0f;

    for (int kt = 0; kt < 36; ++kt) {
        // stage A tile [128 rows x 32 k] fp32 -> split bf16 hi/lo
#pragma unroll
        for (int it = 0; it < 4; ++it) {
            int f   = tid + it * 256;     // 0..1023 float4s
            int row = f >> 3;
            int q   = f & 7;
            int gr  = m0 + row;
            float4 v = make_float4(0.f, 0.f, 0.f, 0.f);
            if (gr < N) v = A4[(size_t)gr * 288 + kt * 8 + q];
            uint32_t h0, l0, h1, l1;
            split2(v.x, v.y, h0, l0);
            split2(v.z, v.w, h1, l1);
            int o = row * AS_STRIDE + q * 4;
            *(uint32_t*)&AsH[o]     = h0;
            *(uint32_t*)&AsH[o + 2] = h1;
            *(uint32_t*)&AsL[o]     = l0;
            *(uint32_t*)&AsL[o + 2] = l1;
        }
        // stage B tile [32 k x 128 n] fp32 -> split bf16 hi/lo
        const float4* Bsrc = (kt < 32)
            ? (const float4*)(weight + (size_t)kt * 32 * 128)
            : (const float4*)(root + (size_t)(kt - 32) * 32 * 128);
#pragma unroll
        for (int it = 0; it < 4; ++it) {
            int f    = tid + it * 256;    // 0..1023
            int krow = f >> 5;
            int n4   = f & 31;
            float4 v = Bsrc[f];
            uint32_t h0, l0, h1, l1;
            split2(v.x, v.y, h0, l0);
            split2(v.z, v.w, h1, l1);
            int o = krow * BS_STRIDE + n4 * 4;
            *(uint32_t*)&BsH[o]     = h0;
            *(uint32_t*)&BsH[o + 2] = h1;
            *(uint32_t*)&BsL[o]     = l0;
            *(uint32_t*)&BsL[o + 2] = l1;
        }
        __syncthreads();

#pragma unroll
        for (int kk = 0; kk < 32; kk += 16) {
            uint32_t ah[2][4], al[2][4];
#pragma unroll
            for (int mi = 0; mi < 2; mi++) {
                int r = wm + mi * 16 + (lane & 15);
                int c = kk + (lane >> 4) * 8;
                LDSM_X4(ah[mi], smem_u32(&AsH[r * AS_STRIDE + c]));
                LDSM_X4(al[mi], smem_u32(&AsL[r * AS_STRIDE + c]));
            }
            uint32_t bh[4][4], bl[4][4];
#pragma unroll
            for (int ni = 0; ni < 4; ni++) {
                int r = kk + (lane & 15);
                int c = wn + ni * 16 + (lane >> 4) * 8;
                LDSM_X4T(bh[ni], smem_u32(&BsH[r * BS_STRIDE + c]));
                LDSM_X4T(bl[ni], smem_u32(&BsL[r * BS_STRIDE + c]));
            }
#pragma unroll
            for (int mi = 0; mi < 2; mi++)
#pragma unroll
                for (int ni = 0; ni < 4; ni++) {
                    MMA_BF16(acc[mi][ni * 2],     ah[mi], bh[ni][0], bh[ni][1]);
                    MMA_BF16(acc[mi][ni * 2],     ah[mi], bl[ni][0], bl[ni][1]);
                    MMA_BF16(acc[mi][ni * 2],     al[mi], bh[ni][0], bh[ni][1]);
                    MMA_BF16(acc[mi][ni * 2 + 1], ah[mi], bh[ni][2], bh[ni][3]);
                    MMA_BF16(acc[mi][ni * 2 + 1], ah[mi], bl[ni][2], bl[ni][3]);
                    MMA_BF16(acc[mi][ni * 2 + 1], al[mi], bh[ni][2], bh[ni][3]);
                }
        }
        __syncthreads();
    }

    // epilogue: fragment (c0,c1)->(r,c),(r,c+1); (c2,c3)->(r+8,c)
    int r0 = lane >> 2;
    int c0 = (lane & 3) * 2;
#pragma unroll
    for (int mi = 0; mi < 2; mi++)
#pragma unroll
        for (int n8 = 0; n8 < 8; n8++) {
            int gn = wn + n8 * 8 + c0;
            float b0 = bias[gn], b1 = bias[gn + 1];
            int gm = m0 + wm + mi * 16 + r0;
            if (gm < N) {
                float2* p = (float2*)(out + (size_t)gm * CH + gn);
                *p = make_float2(acc[mi][n8][0] + b0, acc[mi][n8][1] + b1);
            }
            if (gm + 8 < N) {
                float2* p = (float2*)(out + (size_t)(gm + 8) * CH + gn);
                *p = make_float2(acc[mi][n8][2] + b0, acc[mi][n8][3] + b1);
            }
        }
}

// ---------------- launch ----------------
extern "C" void kernel_launch(void* const* d_in, const int* in_sizes, int n_in,
                              void* d_out, int out_size) {
    const float* x      = (const float*)d_in[0];
    const int*   ei     = (const int*)d_in[1];    // int32 (JAX x64 off)
    const int*   et     = (const int*)d_in[2];
    const float* weight = (const float*)d_in[3];
    const float* root   = (const float*)d_in[4];
    const float* bias   = (const float*)d_in[5];
    float*       out    = (float*)d_out;

    int N  = in_sizes[0] / CH;       // 100000
    int E  = in_sizes[2];            // 1600000
    int RN = NREL * N;
    int nb = (RN + CHUNK - 1) / CHUNK;
    int gemm_blocks = (N + 127) / 128;
    size_t agg_warps = (size_t)N * NSLOT;
    int agg_blocks = (int)((agg_warps * 32 + 255) / 256);

    // CSR build
    zero_cnt_kernel<<<(RN + 255) / 256, 256>>>(RN);
    hist_kernel<<<(E + 255) / 256, 256>>>(ei, et, E, N);
    scan_blocksum_kernel<<<nb, 256>>>(RN);
    scan_offsets_kernel<<<1, 32>>>(nb, RN);
    scan_chunk_kernel<<<nb, 256>>>(RN);
    scatter_edges_kernel<<<(E + 255) / 256, 256>>>(ei, et, E, N);

    // fused aggregation (8 relation means + x copy) -> g_xw [N, 1152]
    aggregate_all_kernel<<<agg_blocks, 256>>>(x, N);

    // single tensor-core GEMM: out = g_xw @ [W_0..W_7; root] + bias
    gemm_kernel<<<gemm_blocks, 256>>>(weight, root, bias, out, N);
}